// round 13
// baseline (speedup 1.0000x reference)
#include <cuda_runtime.h>
#include <cuda_fp16.h>
#include <cstdint>
#include <cstdio>

#define NMAX 100000
#define EMAX 1600000
#define ETMAX (EMAX + NMAX)

// ---------------- scratch (device globals) ----------------------------------
__device__ __align__(256) float g_h1  [(size_t)NMAX * 128];
__device__ __align__(256) float g_agg1[(size_t)NMAX * 128];
__device__ __align__(256) float g_h2 [(size_t)NMAX * 32];
__device__ __align__(256) float g_ssrc1[NMAX * 4];
__device__ __align__(256) float g_sdst1[NMAX * 4];
__device__ __align__(256) float g_ssrc2[NMAX];
__device__ __align__(256) float g_sdst2[NMAX];
__device__ __align__(256) int   g_src[ETMAX];
__device__ __align__(256) int   g_dst[ETMAX];
__device__ __align__(256) int   g_csr_src[ETMAX];
__device__ __align__(256) int   g_deg[NMAX];
__device__ __align__(256) int   g_ebefore[NMAX];
__device__ __align__(256) int   g_rowptr[NMAX];
__device__ __align__(256) int   g_cursor[NMAX];
__device__ __align__(256) int   g_blocksum[512];
__device__ __align__(256) int   g_bsumex[512];
__device__ int g_is64;

// ---------------- helpers ---------------------------------------------------
__device__ __forceinline__ float lrelu(float v) { return v > 0.f ? v : 0.2f * v; }

// ---------------- setup: fused dtype detect + zero deg -----------------------
__global__ void k_init(const int* __restrict__ ei32, int N) {
    int i = blockIdx.x * blockDim.x + threadIdx.x;
    if (i == 0) {
        int all_zero = 1;
        for (int k = 0; k < 64; k++)
            if (ei32[2 * k + 1] != 0) { all_zero = 0; break; }
        g_is64 = all_zero;
    }
    if (i < N) g_deg[i] = 0;
}

__global__ void k_build_edges(const void* __restrict__ ei, int E, int N) {
    int i = blockIdx.x * blockDim.x + threadIdx.x;
    int etot = E + N;
    if (i >= etot) return;
    int s, d;
    if (i < E) {
        if (g_is64) {
            const long long* p = (const long long*)ei;
            s = (int)p[i];
            d = (int)p[(size_t)E + i];
        } else {
            const int* p = (const int*)ei;
            s = p[i];
            d = p[E + i];
        }
        s = min(max(s, 0), N - 1);
        d = min(max(d, 0), N - 1);
    } else {
        s = i - E;
        d = i - E;
    }
    g_src[i] = s;
    g_dst[i] = d;
    atomicAdd(&g_deg[d], 1);
}

// ---------------- exclusive scan of deg --------------------------------------
__global__ void k_scan1(int N) {
    __shared__ int sm[256];
    int t = threadIdx.x;
    int idx = blockIdx.x * 256 + t;
    int v = (idx < N) ? g_deg[idx] : 0;
    sm[t] = v;
    __syncthreads();
#pragma unroll
    for (int off = 1; off < 256; off <<= 1) {
        int add = (t >= off) ? sm[t - off] : 0;
        __syncthreads();
        sm[t] += add;
        __syncthreads();
    }
    if (idx < N) g_ebefore[idx] = sm[t] - v;
    if (t == 255) g_blocksum[blockIdx.x] = sm[255];
}

__global__ void k_scan2(int nb) {
    __shared__ int sm[512];
    int t = threadIdx.x;
    int v = (t < nb) ? g_blocksum[t] : 0;
    sm[t] = v;
    __syncthreads();
#pragma unroll
    for (int off = 1; off < 512; off <<= 1) {
        int add = (t >= off) ? sm[t - off] : 0;
        __syncthreads();
        sm[t] += add;
        __syncthreads();
    }
    if (t < nb) g_bsumex[t] = sm[t] - v;
}

__global__ void k_scan3(int N) {
    int i = blockIdx.x * blockDim.x + threadIdx.x;
    if (i >= N) return;
    int r = g_ebefore[i] + g_bsumex[i >> 8];
    g_rowptr[i] = r;
    g_cursor[i] = r;
}

// ---------------- GEMM1: 128x64 tiles, 3 CTAs/SM -----------------------------
// blockIdx: tile = bid>>1 (128 rows), ch = bid&1 (column half: cols ch*64..+64).
// 256 threads: tx 0..15 (4 cols at tx*4), ty 0..15 (8 rows: ty*4+i, 64+ty*4+i).
// Heads: this block's 64 cols = heads {ch*2, ch*2+1}; attention dots owned
// exclusively (no cross-block combining).
#define XP 136

__global__ __launch_bounds__(256, 3)
void k_gemm1(const float* __restrict__ x, const float* __restrict__ W,
             const float* __restrict__ asrc, const float* __restrict__ adst, int N) {
    __shared__ float xs[2][16 * XP];     // xs[buf][k*XP + row], 128 rows
    __shared__ float ws[2][16 * 64];     // ws[buf][k*64 + c], this col-half
    __shared__ float sa[64], sb[64];
    __shared__ float ssb[128 * 2], sdb[128 * 2];   // per-(row, local head)

    int t = threadIdx.x;
    int tile = blockIdx.x >> 1;
    int ch = blockIdx.x & 1;
    int base = tile * 128;
    int C0 = ch * 64;
    int tx = t & 15, ty = t >> 4;

    if (t < 64) { sa[t] = asrc[C0 + t]; sb[t] = adst[C0 + t]; }
    if (t < 128) { ssb[t] = 0.f; ssb[t + 128] = 0.f; sdb[t] = 0.f; sdb[t + 128] = 0.f; }

    float4 px0, px1, pw0;
    auto ldx = [&](int k0, int id) -> float4 {
        int row = id >> 2, kq = id & 3;
        int gr = base + row;
        if (gr < N) return *reinterpret_cast<const float4*>(x + (size_t)gr * 128 + k0 + kq * 4);
        return make_float4(0.f, 0.f, 0.f, 0.f);
    };
    auto ldw = [&](int k0) -> float4 {
        int k = t >> 4, c = (t & 15) * 4;
        return *reinterpret_cast<const float4*>(W + (size_t)(k0 + k) * 128 + C0 + c);
    };

    px0 = ldx(0, t); px1 = ldx(0, t + 256);
    pw0 = ldw(0);

    float acc[8][4];
#pragma unroll
    for (int i = 0; i < 8; i++)
#pragma unroll
        for (int j = 0; j < 4; j++) acc[i][j] = 0.f;

    auto sts = [&](int buf) {
        {
            int id = t, row = id >> 2, kq = id & 3;
            float* p = &xs[buf][(kq * 4) * XP + row];
            p[0] = px0.x; p[XP] = px0.y; p[2 * XP] = px0.z; p[3 * XP] = px0.w;
        }
        {
            int id = t + 256, row = id >> 2, kq = id & 3;
            float* p = &xs[buf][(kq * 4) * XP + row];
            p[0] = px1.x; p[XP] = px1.y; p[2 * XP] = px1.z; p[3 * XP] = px1.w;
        }
        int k = t >> 4, c = (t & 15) * 4;
        *reinterpret_cast<float4*>(&ws[buf][k * 64 + c]) = pw0;
    };

    sts(0);
    __syncthreads();

#pragma unroll 1
    for (int c = 0; c < 8; c++) {
        int buf = c & 1;
        if (c < 7) {
            int k0 = (c + 1) * 16;
            px0 = ldx(k0, t); px1 = ldx(k0, t + 256);
            pw0 = ldw(k0);
        }
#pragma unroll
        for (int k = 0; k < 16; k++) {
            float4 xa = *reinterpret_cast<const float4*>(&xs[buf][k * XP + ty * 4]);
            float4 xb = *reinterpret_cast<const float4*>(&xs[buf][k * XP + 64 + ty * 4]);
            float4 wv = *reinterpret_cast<const float4*>(&ws[buf][k * 64 + tx * 4]);
            float xv[8] = {xa.x, xa.y, xa.z, xa.w, xb.x, xb.y, xb.z, xb.w};
#pragma unroll
            for (int i = 0; i < 8; i++) {
                acc[i][0] += xv[i] * wv.x;
                acc[i][1] += xv[i] * wv.y;
                acc[i][2] += xv[i] * wv.z;
                acc[i][3] += xv[i] * wv.w;
            }
        }
        __syncthreads();
        if (c < 7) { sts(buf ^ 1); __syncthreads(); }
    }

    // epilogue: h1 stores + attention dots (local heads 0/1 = tx>>3)
    int hl = tx >> 3;
#pragma unroll
    for (int half = 0; half < 2; half++) {
#pragma unroll
        for (int i = 0; i < 4; i++) {
            int r = half * 64 + ty * 4 + i;
            int gr = base + r;
            const float* ai = acc[half * 4 + i];
            if (gr < N)
                *reinterpret_cast<float4*>(g_h1 + (size_t)gr * 128 + C0 + tx * 4) =
                    make_float4(ai[0], ai[1], ai[2], ai[3]);
            float ss = ai[0] * sa[tx * 4] + ai[1] * sa[tx * 4 + 1] + ai[2] * sa[tx * 4 + 2] + ai[3] * sa[tx * 4 + 3];
            float sd = ai[0] * sb[tx * 4] + ai[1] * sb[tx * 4 + 1] + ai[2] * sb[tx * 4 + 2] + ai[3] * sb[tx * 4 + 3];
            atomicAdd(&ssb[r * 2 + hl], ss);
            atomicAdd(&sdb[r * 2 + hl], sd);
        }
    }
    __syncthreads();
    if (t < 128) {
        int gr = base + t;
        if (gr < N) {
            *reinterpret_cast<float2*>(g_ssrc1 + (size_t)gr * 4 + ch * 2) =
                *reinterpret_cast<const float2*>(ssb + t * 2);
            *reinterpret_cast<float2*>(g_sdst1 + (size_t)gr * 4 + ch * 2) =
                *reinterpret_cast<const float2*>(sdb + t * 2);
        }
    }
}

// ---------------- CSR scatter: pure permutation ------------------------------
__global__ void k_scatter(int etot) {
    int i = blockIdx.x * blockDim.x + threadIdx.x;
    if (i >= etot) return;
    int d = g_dst[i];
    int pos = atomicAdd(&g_cursor[d], 1);
    g_csr_src[pos] = g_src[i];
}

// ---------------- layer 1 aggregation: warp/dst, single pass (proven best) --
__global__ void k_agg1(int N) {
    int w = (blockIdx.x * blockDim.x + threadIdx.x) >> 5;
    if (w >= N) return;
    int lane = threadIdx.x & 31;
    int h = lane >> 3, c0 = lane * 4;
    int deg = g_deg[w], start = g_rowptr[w];
    float sd = __ldg(&g_sdst1[(size_t)w * 4 + h]);

    float4 acc = make_float4(0.f, 0.f, 0.f, 0.f);
    float den = 0.f;

    int j = 0;
    for (; j + 2 <= deg; j += 2) {
        int s0 = __ldg(&g_csr_src[start + j]);
        int s1 = __ldg(&g_csr_src[start + j + 1]);
        float ss0 = __ldg(&g_ssrc1[(size_t)s0 * 4 + h]);
        float ss1 = __ldg(&g_ssrc1[(size_t)s1 * 4 + h]);
        float4 hv0 = *reinterpret_cast<const float4*>(g_h1 + (size_t)s0 * 128 + c0);
        float4 hv1 = *reinterpret_cast<const float4*>(g_h1 + (size_t)s1 * 128 + c0);
        float e0 = __expf(lrelu(ss0 + sd));
        float e1 = __expf(lrelu(ss1 + sd));
        den += e0 + e1;
        acc.x += e0 * hv0.x + e1 * hv1.x;
        acc.y += e0 * hv0.y + e1 * hv1.y;
        acc.z += e0 * hv0.z + e1 * hv1.z;
        acc.w += e0 * hv0.w + e1 * hv1.w;
    }
    for (; j < deg; j++) {
        int s = __ldg(&g_csr_src[start + j]);
        float ss = __ldg(&g_ssrc1[(size_t)s * 4 + h]);
        float e = __expf(lrelu(ss + sd));
        den += e;
        float4 hv = *reinterpret_cast<const float4*>(g_h1 + (size_t)s * 128 + c0);
        acc.x += e * hv.x;
        acc.y += e * hv.y;
        acc.z += e * hv.z;
        acc.w += e * hv.w;
    }
    float inv = 1.f / (den + 1e-16f);
    acc.x *= inv; acc.y *= inv; acc.z *= inv; acc.w *= inv;
    *reinterpret_cast<float4*>(g_agg1 + (size_t)w * 128 + c0) = acc;
}

// ---------------- layer 2 node kernel: elu + GEMM, M=128 tiles --------------
#define XP2 264

__global__ __launch_bounds__(256, 2)
void k_layer2_node(const float* __restrict__ b1, const float* __restrict__ W2,
                   const float* __restrict__ asrc2, const float* __restrict__ adst2,
                   int N) {
    __shared__ float xs[16 * XP2];
    __shared__ float ws[128 * 32];
    __shared__ float sb1[128];
    __shared__ float sa[32], sb[32];

    int t = threadIdx.x;
    int base = blockIdx.x * 128;
    int tx = t & 7, ty = t >> 3;

    if (t < 128) sb1[t] = b1[t];
    if (t < 32) { sa[t] = asrc2[t]; sb[t] = adst2[t]; }
    for (int i = t; i < 1024; i += 256)
        reinterpret_cast<float4*>(ws)[i] = reinterpret_cast<const float4*>(W2)[i];

    float4 pf[2];
    auto ldx = [&](int k0, int id) -> float4 {
        int row = id >> 2, kq = id & 3;
        int gr = base + row;
        float4 v = make_float4(0.f, 0.f, 0.f, 0.f);
        if (gr < N) {
            v = *reinterpret_cast<const float4*>(g_agg1 + (size_t)gr * 128 + k0 + kq * 4);
            v.x += sb1[k0 + kq * 4];     v.x = v.x > 0.f ? v.x : expm1f(v.x);
            v.y += sb1[k0 + kq * 4 + 1]; v.y = v.y > 0.f ? v.y : expm1f(v.y);
            v.z += sb1[k0 + kq * 4 + 2]; v.z = v.z > 0.f ? v.z : expm1f(v.z);
            v.w += sb1[k0 + kq * 4 + 3]; v.w = v.w > 0.f ? v.w : expm1f(v.w);
        }
        return v;
    };
    __syncthreads();

#pragma unroll
    for (int j = 0; j < 2; j++) pf[j] = ldx(0, t + 256 * j);

    float acc[4][4];
#pragma unroll
    for (int i = 0; i < 4; i++)
#pragma unroll
        for (int j = 0; j < 4; j++) acc[i][j] = 0.f;

#pragma unroll 1
    for (int c = 0; c < 8; c++) {
        __syncthreads();
#pragma unroll
        for (int j = 0; j < 2; j++) {
            int id = t + 256 * j, row = id >> 2, kq = id & 3;
            float* p = &xs[(kq * 4) * XP2 + row];
            p[0] = pf[j].x; p[XP2] = pf[j].y; p[2 * XP2] = pf[j].z; p[3 * XP2] = pf[j].w;
        }
        __syncthreads();
        if (c < 7) {
            int k0 = (c + 1) * 16;
#pragma unroll
            for (int j = 0; j < 2; j++) pf[j] = ldx(k0, t + 256 * j);
        }
        int kb = c * 16;
#pragma unroll
        for (int k = 0; k < 16; k++) {
            float4 xa = *reinterpret_cast<const float4*>(&xs[k * XP2 + ty * 4]);
            float4 wv = *reinterpret_cast<const float4*>(&ws[(kb + k) * 32 + tx * 4]);
            float xv[4] = {xa.x, xa.y, xa.z, xa.w};
#pragma unroll
            for (int i = 0; i < 4; i++) {
                acc[i][0] += xv[i] * wv.x;
                acc[i][1] += xv[i] * wv.y;
                acc[i][2] += xv[i] * wv.z;
                acc[i][3] += xv[i] * wv.w;
            }
        }
    }

#pragma unroll
    for (int i = 0; i < 4; i++) {
        int r = ty * 4 + i;
        int gr = base + r;
        const float* ai = acc[i];
        if (gr < N)
            *reinterpret_cast<float4*>(g_h2 + (size_t)gr * 32 + tx * 4) =
                make_float4(ai[0], ai[1], ai[2], ai[3]);
        float ps = ai[0] * sa[tx * 4] + ai[1] * sa[tx * 4 + 1] + ai[2] * sa[tx * 4 + 2] + ai[3] * sa[tx * 4 + 3];
        float pd = ai[0] * sb[tx * 4] + ai[1] * sb[tx * 4 + 1] + ai[2] * sb[tx * 4 + 2] + ai[3] * sb[tx * 4 + 3];
#pragma unroll
        for (int off = 4; off; off >>= 1) {
            ps += __shfl_xor_sync(0xffffffffu, ps, off);
            pd += __shfl_xor_sync(0xffffffffu, pd, off);
        }
        if (tx == 0 && gr < N) { g_ssrc2[gr] = ps; g_sdst2[gr] = pd; }
    }
}

// ---------------- layer 2 aggregation: warp/dst, unroll-4, fused bias -------
__global__ void k_agg2(float* __restrict__ out, const float* __restrict__ b2, int N) {
    int w = (blockIdx.x * blockDim.x + threadIdx.x) >> 5;
    if (w >= N) return;
    int lane = threadIdx.x & 31;
    int deg = g_deg[w], start = g_rowptr[w];
    float sd = __ldg(&g_sdst2[w]);

    float acc = 0.f, den = 0.f;
    int j = 0;
    for (; j + 4 <= deg; j += 4) {
        int s0 = __ldg(&g_csr_src[start + j]);
        int s1 = __ldg(&g_csr_src[start + j + 1]);
        int s2 = __ldg(&g_csr_src[start + j + 2]);
        int s3 = __ldg(&g_csr_src[start + j + 3]);
        float a0 = __ldg(&g_ssrc2[s0]);
        float a1 = __ldg(&g_ssrc2[s1]);
        float a2 = __ldg(&g_ssrc2[s2]);
        float a3 = __ldg(&g_ssrc2[s3]);
        float v0 = __ldg(&g_h2[(size_t)s0 * 32 + lane]);
        float v1 = __ldg(&g_h2[(size_t)s1 * 32 + lane]);
        float v2 = __ldg(&g_h2[(size_t)s2 * 32 + lane]);
        float v3 = __ldg(&g_h2[(size_t)s3 * 32 + lane]);
        float e0 = __expf(lrelu(a0 + sd));
        float e1 = __expf(lrelu(a1 + sd));
        float e2 = __expf(lrelu(a2 + sd));
        float e3 = __expf(lrelu(a3 + sd));
        den += (e0 + e1) + (e2 + e3);
        acc += e0 * v0 + e1 * v1 + e2 * v2 + e3 * v3;
    }
    for (; j < deg; j++) {
        int s = __ldg(&g_csr_src[start + j]);
        float e = __expf(lrelu(__ldg(&g_ssrc2[s]) + sd));
        den += e;
        acc += e * __ldg(&g_h2[(size_t)s * 32 + lane]);
    }
    out[(size_t)w * 32 + lane] = acc / (den + 1e-16f) + __ldg(&b2[lane]);
}

// ---------------- launch -----------------------------------------------------
static cudaStream_t g_s2 = nullptr;
static cudaEvent_t  g_evFork = nullptr, g_evJoin = nullptr;

extern "C" void kernel_launch(void* const* d_in, const int* in_sizes, int n_in,
                              void* d_out, int out_size) {
    const float* x     = (const float*)d_in[0];
    const void*  ei    = d_in[1];
    const float* W1    = (const float*)d_in[2];
    const float* asrc1 = (const float*)d_in[3];
    const float* adst1 = (const float*)d_in[4];
    const float* b1    = (const float*)d_in[5];
    const float* W2    = (const float*)d_in[6];
    const float* asrc2 = (const float*)d_in[7];
    const float* adst2 = (const float*)d_in[8];
    const float* b2    = (const float*)d_in[9];
    float* out = (float*)d_out;

    int N = in_sizes[0] / 128;
    int E = in_sizes[1] / 2;
    if (N > NMAX) N = NMAX;
    if (E > EMAX) E = EMAX;
    int etot = E + N;
    int nb = (N + 255) / 256;

    if (g_s2 == nullptr) {
        cudaStreamCreateWithFlags(&g_s2, cudaStreamNonBlocking);
        cudaEventCreateWithFlags(&g_evFork, cudaEventDisableTiming);
        cudaEventCreateWithFlags(&g_evJoin, cudaEventDisableTiming);
    }

    // fork: CSR-build chain on s2, concurrent with gemm1 on main stream
    cudaEventRecord(g_evFork, 0);
    cudaStreamWaitEvent(g_s2, g_evFork, 0);

    k_init<<<(N + 255) / 256, 256, 0, g_s2>>>((const int*)ei, N);
    k_build_edges<<<(etot + 255) / 256, 256, 0, g_s2>>>(ei, E, N);
    k_scan1<<<nb, 256, 0, g_s2>>>(N);
    k_scan2<<<1, 512, 0, g_s2>>>(nb);
    k_scan3<<<(N + 255) / 256, 256, 0, g_s2>>>(N);
    k_scatter<<<(etot + 255) / 256, 256, 0, g_s2>>>(etot);
    cudaEventRecord(g_evJoin, g_s2);

    // main stream: gemm1 concurrent with chain (2 blocks per 128-row tile)
    k_gemm1<<<((N + 127) / 128) * 2, 256>>>(x, W1, asrc1, adst1, N);

    // join, then dependent pipeline
    cudaStreamWaitEvent(0, g_evJoin, 0);
    k_agg1<<<(int)(((long long)N * 32 + 255) / 256), 256>>>(N);
    k_layer2_node<<<(N + 127) / 128, 256>>>(b1, W2, asrc2, adst2, N);
    k_agg2<<<(int)(((long long)N * 32 + 255) / 256), 256>>>(out, b2, N);
}

// round 14
// speedup vs baseline: 1.5491x; 1.5491x over previous
#include <cuda_runtime.h>
#include <cuda_fp16.h>
#include <cstdint>
#include <cstdio>

#define NMAX 100000
#define EMAX 1600000
#define ETMAX (EMAX + NMAX)

// ---------------- scratch (device globals) ----------------------------------
__device__ __align__(256) float g_h1  [(size_t)NMAX * 128];
__device__ __align__(256) float g_agg1[(size_t)NMAX * 128];
__device__ __align__(256) float g_h2 [(size_t)NMAX * 32];
__device__ __align__(256) float g_ssrc1[NMAX * 4];
__device__ __align__(256) float g_sdst1[NMAX * 4];
__device__ __align__(256) float g_ssrc2[NMAX];
__device__ __align__(256) float g_sdst2[NMAX];
__device__ __align__(256) int   g_src[ETMAX];
__device__ __align__(256) int   g_dst[ETMAX];
__device__ __align__(256) int   g_csr_src[ETMAX];
__device__ __align__(256) int   g_deg[NMAX];
__device__ __align__(256) int   g_ebefore[NMAX];
__device__ __align__(256) int   g_rowptr[NMAX];
__device__ __align__(256) int   g_cursor[NMAX];
__device__ __align__(256) int   g_blocksum[512];
__device__ __align__(256) int   g_bsumex[512];
__device__ int g_is64;

// ---------------- helpers ---------------------------------------------------
__device__ __forceinline__ float lrelu(float v) { return v > 0.f ? v : 0.2f * v; }

// ---------------- setup: fused dtype detect + zero deg -----------------------
__global__ void k_init(const int* __restrict__ ei32, int N) {
    int i = blockIdx.x * blockDim.x + threadIdx.x;
    if (i == 0) {
        int all_zero = 1;
        for (int k = 0; k < 64; k++)
            if (ei32[2 * k + 1] != 0) { all_zero = 0; break; }
        g_is64 = all_zero;
    }
    if (i < N) g_deg[i] = 0;
}

__global__ void k_build_edges(const void* __restrict__ ei, int E, int N) {
    int i = blockIdx.x * blockDim.x + threadIdx.x;
    int etot = E + N;
    if (i >= etot) return;
    int s, d;
    if (i < E) {
        if (g_is64) {
            const long long* p = (const long long*)ei;
            s = (int)p[i];
            d = (int)p[(size_t)E + i];
        } else {
            const int* p = (const int*)ei;
            s = p[i];
            d = p[E + i];
        }
        s = min(max(s, 0), N - 1);
        d = min(max(d, 0), N - 1);
    } else {
        s = i - E;
        d = i - E;
    }
    g_src[i] = s;
    g_dst[i] = d;
    atomicAdd(&g_deg[d], 1);
}

// ---------------- exclusive scan of deg --------------------------------------
__global__ void k_scan1(int N) {
    __shared__ int sm[256];
    int t = threadIdx.x;
    int idx = blockIdx.x * 256 + t;
    int v = (idx < N) ? g_deg[idx] : 0;
    sm[t] = v;
    __syncthreads();
#pragma unroll
    for (int off = 1; off < 256; off <<= 1) {
        int add = (t >= off) ? sm[t - off] : 0;
        __syncthreads();
        sm[t] += add;
        __syncthreads();
    }
    if (idx < N) g_ebefore[idx] = sm[t] - v;
    if (t == 255) g_blocksum[blockIdx.x] = sm[255];
}

__global__ void k_scan2(int nb) {
    __shared__ int sm[512];
    int t = threadIdx.x;
    int v = (t < nb) ? g_blocksum[t] : 0;
    sm[t] = v;
    __syncthreads();
#pragma unroll
    for (int off = 1; off < 512; off <<= 1) {
        int add = (t >= off) ? sm[t - off] : 0;
        __syncthreads();
        sm[t] += add;
        __syncthreads();
    }
    if (t < nb) g_bsumex[t] = sm[t] - v;
}

__global__ void k_scan3(int N) {
    int i = blockIdx.x * blockDim.x + threadIdx.x;
    if (i >= N) return;
    int r = g_ebefore[i] + g_bsumex[i >> 8];
    g_rowptr[i] = r;
    g_cursor[i] = r;
}

// ---------------- GEMM1: register-blocked 128x128 tile ----------------------
#define XP 136

__global__ __launch_bounds__(256, 2)
void k_gemm1(const float* __restrict__ x, const float* __restrict__ W,
             const float* __restrict__ asrc, const float* __restrict__ adst, int N) {
    __shared__ float xs[2][16 * XP];
    __shared__ float ws[2][16 * 128];
    __shared__ float sa[128], sb[128];
    __shared__ float ssb[128 * 4], sdb[128 * 4];

    int t = threadIdx.x;
    int base = blockIdx.x * 128;
    int tx = t & 15, ty = t >> 4;

    if (t < 128) { sa[t] = asrc[t]; sb[t] = adst[t]; }
    ssb[t] = 0.f; ssb[t + 256] = 0.f;
    sdb[t] = 0.f; sdb[t + 256] = 0.f;

    const float4* W4 = reinterpret_cast<const float4*>(W);

    float4 px0, px1, pw0, pw1;
    auto ldx = [&](int k0, int id) -> float4 {
        int row = id >> 2, kq = id & 3;
        int gr = base + row;
        if (gr < N) return *reinterpret_cast<const float4*>(x + (size_t)gr * 128 + k0 + kq * 4);
        return make_float4(0.f, 0.f, 0.f, 0.f);
    };

    px0 = ldx(0, t); px1 = ldx(0, t + 256);
    pw0 = W4[t]; pw1 = W4[t + 256];

    float acc[8][8];
#pragma unroll
    for (int i = 0; i < 8; i++)
#pragma unroll
        for (int j = 0; j < 8; j++) acc[i][j] = 0.f;

    auto sts = [&](int buf) {
        {
            int id = t, row = id >> 2, kq = id & 3;
            float* p = &xs[buf][(kq * 4) * XP + row];
            p[0] = px0.x; p[XP] = px0.y; p[2 * XP] = px0.z; p[3 * XP] = px0.w;
        }
        {
            int id = t + 256, row = id >> 2, kq = id & 3;
            float* p = &xs[buf][(kq * 4) * XP + row];
            p[0] = px1.x; p[XP] = px1.y; p[2 * XP] = px1.z; p[3 * XP] = px1.w;
        }
        reinterpret_cast<float4*>(ws[buf])[t] = pw0;
        reinterpret_cast<float4*>(ws[buf])[t + 256] = pw1;
    };

    sts(0);
    __syncthreads();

#pragma unroll 1
    for (int c = 0; c < 8; c++) {
        int buf = c & 1;
        if (c < 7) {
            int k0 = (c + 1) * 16;
            px0 = ldx(k0, t); px1 = ldx(k0, t + 256);
            pw0 = W4[k0 * 32 + t]; pw1 = W4[k0 * 32 + t + 256];
        }
#pragma unroll
        for (int k = 0; k < 16; k++) {
            float4 xa = *reinterpret_cast<const float4*>(&xs[buf][k * XP + ty * 4]);
            float4 xb = *reinterpret_cast<const float4*>(&xs[buf][k * XP + 64 + ty * 4]);
            float4 wa = *reinterpret_cast<const float4*>(&ws[buf][k * 128 + tx * 4]);
            float4 wb = *reinterpret_cast<const float4*>(&ws[buf][k * 128 + 64 + tx * 4]);
            float xv[8] = {xa.x, xa.y, xa.z, xa.w, xb.x, xb.y, xb.z, xb.w};
            float wv[8] = {wa.x, wa.y, wa.z, wa.w, wb.x, wb.y, wb.z, wb.w};
#pragma unroll
            for (int i = 0; i < 8; i++)
#pragma unroll
                for (int j = 0; j < 8; j++)
                    acc[i][j] += xv[i] * wv[j];
        }
        __syncthreads();
        if (c < 7) { sts(buf ^ 1); __syncthreads(); }
    }

    int hlo = tx >> 3;
    int hhi = 2 + (tx >> 3);
#pragma unroll
    for (int half = 0; half < 2; half++) {
        int rbase = half * 64 + ty * 4;
#pragma unroll
        for (int i = 0; i < 4; i++) {
            int r = rbase + i;
            int gr = base + r;
            const float* ai = acc[half * 4 + i];
            if (gr < N) {
                *reinterpret_cast<float4*>(g_h1 + (size_t)gr * 128 + tx * 4) =
                    make_float4(ai[0], ai[1], ai[2], ai[3]);
                *reinterpret_cast<float4*>(g_h1 + (size_t)gr * 128 + 64 + tx * 4) =
                    make_float4(ai[4], ai[5], ai[6], ai[7]);
            }
            float ssl = ai[0] * sa[tx * 4] + ai[1] * sa[tx * 4 + 1] + ai[2] * sa[tx * 4 + 2] + ai[3] * sa[tx * 4 + 3];
            float ssh = ai[4] * sa[64 + tx * 4] + ai[5] * sa[64 + tx * 4 + 1] + ai[6] * sa[64 + tx * 4 + 2] + ai[7] * sa[64 + tx * 4 + 3];
            float sdl = ai[0] * sb[tx * 4] + ai[1] * sb[tx * 4 + 1] + ai[2] * sb[tx * 4 + 2] + ai[3] * sb[tx * 4 + 3];
            float sdh = ai[4] * sb[64 + tx * 4] + ai[5] * sb[64 + tx * 4 + 1] + ai[6] * sb[64 + tx * 4 + 2] + ai[7] * sb[64 + tx * 4 + 3];
            atomicAdd(&ssb[r * 4 + hlo], ssl);
            atomicAdd(&ssb[r * 4 + hhi], ssh);
            atomicAdd(&sdb[r * 4 + hlo], sdl);
            atomicAdd(&sdb[r * 4 + hhi], sdh);
        }
    }
    __syncthreads();
    if (t < 128) {
        int gr = base + t;
        if (gr < N) {
            *reinterpret_cast<float4*>(g_ssrc1 + (size_t)gr * 4) =
                *reinterpret_cast<const float4*>(ssb + t * 4);
            *reinterpret_cast<float4*>(g_sdst1 + (size_t)gr * 4) =
                *reinterpret_cast<const float4*>(sdb + t * 4);
        }
    }
}

// ---------------- CSR scatter: pure permutation ------------------------------
__global__ void k_scatter(int etot) {
    int i = blockIdx.x * blockDim.x + threadIdx.x;
    if (i >= etot) return;
    int d = g_dst[i];
    int pos = atomicAdd(&g_cursor[d], 1);
    g_csr_src[pos] = g_src[i];
}

// ---------------- layer 1 aggregation: warp/dst, single pass (proven best) --
__global__ void k_agg1(int N) {
    int w = (blockIdx.x * blockDim.x + threadIdx.x) >> 5;
    if (w >= N) return;
    int lane = threadIdx.x & 31;
    int h = lane >> 3, c0 = lane * 4;
    int deg = g_deg[w], start = g_rowptr[w];
    float sd = __ldg(&g_sdst1[(size_t)w * 4 + h]);

    float4 acc = make_float4(0.f, 0.f, 0.f, 0.f);
    float den = 0.f;

    int j = 0;
    for (; j + 2 <= deg; j += 2) {
        int s0 = __ldg(&g_csr_src[start + j]);
        int s1 = __ldg(&g_csr_src[start + j + 1]);
        float ss0 = __ldg(&g_ssrc1[(size_t)s0 * 4 + h]);
        float ss1 = __ldg(&g_ssrc1[(size_t)s1 * 4 + h]);
        float4 hv0 = *reinterpret_cast<const float4*>(g_h1 + (size_t)s0 * 128 + c0);
        float4 hv1 = *reinterpret_cast<const float4*>(g_h1 + (size_t)s1 * 128 + c0);
        float e0 = __expf(lrelu(ss0 + sd));
        float e1 = __expf(lrelu(ss1 + sd));
        den += e0 + e1;
        acc.x += e0 * hv0.x + e1 * hv1.x;
        acc.y += e0 * hv0.y + e1 * hv1.y;
        acc.z += e0 * hv0.z + e1 * hv1.z;
        acc.w += e0 * hv0.w + e1 * hv1.w;
    }
    for (; j < deg; j++) {
        int s = __ldg(&g_csr_src[start + j]);
        float ss = __ldg(&g_ssrc1[(size_t)s * 4 + h]);
        float e = __expf(lrelu(ss + sd));
        den += e;
        float4 hv = *reinterpret_cast<const float4*>(g_h1 + (size_t)s * 128 + c0);
        acc.x += e * hv.x;
        acc.y += e * hv.y;
        acc.z += e * hv.z;
        acc.w += e * hv.w;
    }
    float inv = 1.f / (den + 1e-16f);
    acc.x *= inv; acc.y *= inv; acc.z *= inv; acc.w *= inv;
    *reinterpret_cast<float4*>(g_agg1 + (size_t)w * 128 + c0) = acc;
}

// ---------------- layer 2 node kernel: elu + GEMM, M=128 tiles --------------
#define XP2 264

__global__ __launch_bounds__(256, 2)
void k_layer2_node(const float* __restrict__ b1, const float* __restrict__ W2,
                   const float* __restrict__ asrc2, const float* __restrict__ adst2,
                   int N) {
    __shared__ float xs[16 * XP2];
    __shared__ float ws[128 * 32];
    __shared__ float sb1[128];
    __shared__ float sa[32], sb[32];

    int t = threadIdx.x;
    int base = blockIdx.x * 128;
    int tx = t & 7, ty = t >> 3;

    if (t < 128) sb1[t] = b1[t];
    if (t < 32) { sa[t] = asrc2[t]; sb[t] = adst2[t]; }
    for (int i = t; i < 1024; i += 256)
        reinterpret_cast<float4*>(ws)[i] = reinterpret_cast<const float4*>(W2)[i];

    float4 pf[2];
    auto ldx = [&](int k0, int id) -> float4 {
        int row = id >> 2, kq = id & 3;
        int gr = base + row;
        float4 v = make_float4(0.f, 0.f, 0.f, 0.f);
        if (gr < N) {
            v = *reinterpret_cast<const float4*>(g_agg1 + (size_t)gr * 128 + k0 + kq * 4);
            v.x += sb1[k0 + kq * 4];     v.x = v.x > 0.f ? v.x : expm1f(v.x);
            v.y += sb1[k0 + kq * 4 + 1]; v.y = v.y > 0.f ? v.y : expm1f(v.y);
            v.z += sb1[k0 + kq * 4 + 2]; v.z = v.z > 0.f ? v.z : expm1f(v.z);
            v.w += sb1[k0 + kq * 4 + 3]; v.w = v.w > 0.f ? v.w : expm1f(v.w);
        }
        return v;
    };
    __syncthreads();

#pragma unroll
    for (int j = 0; j < 2; j++) pf[j] = ldx(0, t + 256 * j);

    float acc[4][4];
#pragma unroll
    for (int i = 0; i < 4; i++)
#pragma unroll
        for (int j = 0; j < 4; j++) acc[i][j] = 0.f;

#pragma unroll 1
    for (int c = 0; c < 8; c++) {
        __syncthreads();
#pragma unroll
        for (int j = 0; j < 2; j++) {
            int id = t + 256 * j, row = id >> 2, kq = id & 3;
            float* p = &xs[(kq * 4) * XP2 + row];
            p[0] = pf[j].x; p[XP2] = pf[j].y; p[2 * XP2] = pf[j].z; p[3 * XP2] = pf[j].w;
        }
        __syncthreads();
        if (c < 7) {
            int k0 = (c + 1) * 16;
#pragma unroll
            for (int j = 0; j < 2; j++) pf[j] = ldx(k0, t + 256 * j);
        }
        int kb = c * 16;
#pragma unroll
        for (int k = 0; k < 16; k++) {
            float4 xa = *reinterpret_cast<const float4*>(&xs[k * XP2 + ty * 4]);
            float4 wv = *reinterpret_cast<const float4*>(&ws[(kb + k) * 32 + tx * 4]);
            float xv[4] = {xa.x, xa.y, xa.z, xa.w};
#pragma unroll
            for (int i = 0; i < 4; i++) {
                acc[i][0] += xv[i] * wv.x;
                acc[i][1] += xv[i] * wv.y;
                acc[i][2] += xv[i] * wv.z;
                acc[i][3] += xv[i] * wv.w;
            }
        }
    }

#pragma unroll
    for (int i = 0; i < 4; i++) {
        int r = ty * 4 + i;
        int gr = base + r;
        const float* ai = acc[i];
        if (gr < N)
            *reinterpret_cast<float4*>(g_h2 + (size_t)gr * 32 + tx * 4) =
                make_float4(ai[0], ai[1], ai[2], ai[3]);
        float ps = ai[0] * sa[tx * 4] + ai[1] * sa[tx * 4 + 1] + ai[2] * sa[tx * 4 + 2] + ai[3] * sa[tx * 4 + 3];
        float pd = ai[0] * sb[tx * 4] + ai[1] * sb[tx * 4 + 1] + ai[2] * sb[tx * 4 + 2] + ai[3] * sb[tx * 4 + 3];
#pragma unroll
        for (int off = 4; off; off >>= 1) {
            ps += __shfl_xor_sync(0xffffffffu, ps, off);
            pd += __shfl_xor_sync(0xffffffffu, pd, off);
        }
        if (tx == 0 && gr < N) { g_ssrc2[gr] = ps; g_sdst2[gr] = pd; }
    }
}

// ---------------- layer 2 aggregation: warp/dst, unroll-4, fused bias -------
__global__ void k_agg2(float* __restrict__ out, const float* __restrict__ b2, int N) {
    int w = (blockIdx.x * blockDim.x + threadIdx.x) >> 5;
    if (w >= N) return;
    int lane = threadIdx.x & 31;
    int deg = g_deg[w], start = g_rowptr[w];
    float sd = __ldg(&g_sdst2[w]);

    float acc = 0.f, den = 0.f;
    int j = 0;
    for (; j + 4 <= deg; j += 4) {
        int s0 = __ldg(&g_csr_src[start + j]);
        int s1 = __ldg(&g_csr_src[start + j + 1]);
        int s2 = __ldg(&g_csr_src[start + j + 2]);
        int s3 = __ldg(&g_csr_src[start + j + 3]);
        float a0 = __ldg(&g_ssrc2[s0]);
        float a1 = __ldg(&g_ssrc2[s1]);
        float a2 = __ldg(&g_ssrc2[s2]);
        float a3 = __ldg(&g_ssrc2[s3]);
        float v0 = __ldg(&g_h2[(size_t)s0 * 32 + lane]);
        float v1 = __ldg(&g_h2[(size_t)s1 * 32 + lane]);
        float v2 = __ldg(&g_h2[(size_t)s2 * 32 + lane]);
        float v3 = __ldg(&g_h2[(size_t)s3 * 32 + lane]);
        float e0 = __expf(lrelu(a0 + sd));
        float e1 = __expf(lrelu(a1 + sd));
        float e2 = __expf(lrelu(a2 + sd));
        float e3 = __expf(lrelu(a3 + sd));
        den += (e0 + e1) + (e2 + e3);
        acc += e0 * v0 + e1 * v1 + e2 * v2 + e3 * v3;
    }
    for (; j < deg; j++) {
        int s = __ldg(&g_csr_src[start + j]);
        float e = __expf(lrelu(__ldg(&g_ssrc2[s]) + sd));
        den += e;
        acc += e * __ldg(&g_h2[(size_t)s * 32 + lane]);
    }
    out[(size_t)w * 32 + lane] = acc / (den + 1e-16f) + __ldg(&b2[lane]);
}

// ---------------- launch -----------------------------------------------------
static cudaStream_t g_s2 = nullptr;
static cudaEvent_t  g_evFork = nullptr, g_evJoin = nullptr;

extern "C" void kernel_launch(void* const* d_in, const int* in_sizes, int n_in,
                              void* d_out, int out_size) {
    const float* x     = (const float*)d_in[0];
    const void*  ei    = d_in[1];
    const float* W1    = (const float*)d_in[2];
    const float* asrc1 = (const float*)d_in[3];
    const float* adst1 = (const float*)d_in[4];
    const float* b1    = (const float*)d_in[5];
    const float* W2    = (const float*)d_in[6];
    const float* asrc2 = (const float*)d_in[7];
    const float* adst2 = (const float*)d_in[8];
    const float* b2    = (const float*)d_in[9];
    float* out = (float*)d_out;

    int N = in_sizes[0] / 128;
    int E = in_sizes[1] / 2;
    if (N > NMAX) N = NMAX;
    if (E > EMAX) E = EMAX;
    int etot = E + N;
    int nb = (N + 255) / 256;

    if (g_s2 == nullptr) {
        cudaStreamCreateWithFlags(&g_s2, cudaStreamNonBlocking);
        cudaEventCreateWithFlags(&g_evFork, cudaEventDisableTiming);
        cudaEventCreateWithFlags(&g_evJoin, cudaEventDisableTiming);
    }

    // fork: CSR-build chain on s2, concurrent with gemm1 on main stream
    cudaEventRecord(g_evFork, 0);
    cudaStreamWaitEvent(g_s2, g_evFork, 0);

    k_init<<<(N + 255) / 256, 256, 0, g_s2>>>((const int*)ei, N);
    k_build_edges<<<(etot + 255) / 256, 256, 0, g_s2>>>(ei, E, N);
    k_scan1<<<nb, 256, 0, g_s2>>>(N);
    k_scan2<<<1, 512, 0, g_s2>>>(nb);
    k_scan3<<<(N + 255) / 256, 256, 0, g_s2>>>(N);
    k_scatter<<<(etot + 255) / 256, 256, 0, g_s2>>>(etot);
    cudaEventRecord(g_evJoin, g_s2);

    // main stream: gemm1 concurrent with chain
    k_gemm1<<<(N + 127) / 128, 256>>>(x, W1, asrc1, adst1, N);

    // join, then dependent pipeline
    cudaStreamWaitEvent(0, g_evJoin, 0);
    k_agg1<<<(int)(((long long)N * 32 + 255) / 256), 256>>>(N);
    k_layer2_node<<<(N + 127) / 128, 256>>>(b1, W2, asrc2, adst2, N);
    k_agg2<<<(int)(((long long)N * 32 + 255) / 256), 256>>>(out, b2, N);
}